// round 8
// baseline (speedup 1.0000x reference)
#include <cuda_runtime.h>
#include <cuda_bf16.h>
#include <mma.h>
#include <cstdint>
#include <math.h>

using namespace nvcuda;

#define NN 50000
#define NE 800000
#define IND 256
#define FDIM 256       // 2 heads * 128
#define SCAN_BLKS 49   // ceil(NN / 1024)
#define BM 64
#define GEMM_BLKS 782  // ceil(NN / 64)
#define XS_LD 48       // bf16 elements per xs row (96B, 32B-aligned rows)
#define WS_LD 272      // bf16 elements per ws row (544B)
#define ACC_LD 264     // fp32 elements per accs row (1056B)
#define SMEM_DYN 67584 // max(47104 mainloop, 64*264*4 epilogue)

// ---------------- scratch (static __device__, no allocation) ----------------
__device__ float g_Wh[NN * FDIM];   // 51.2 MB - fits L2
__device__ float g_s[NN * 2];
__device__ float g_t[NN * 2];
__device__ __align__(16) int g_deg[NN];
__device__ __align__(16) int g_off[NN + 4];
__device__ __align__(16) int g_cur[NN];
__device__ int g_dst[NE];
__device__ int g_bsum[64];
__device__ int g_bpre[64];

// ---------------- CSR build ----------------
__global__ void k_zero() {
    int i = blockIdx.x * blockDim.x + threadIdx.x;
    if (i < NN) g_deg[i] = 0;
}

__global__ void k_count(const int* __restrict__ ei) {
    int e = blockIdx.x * blockDim.x + threadIdx.x;
    if (e < NE) {
        unsigned s = (unsigned)ei[e];
        if (s < NN) atomicAdd(&g_deg[s], 1);
    }
}

__global__ __launch_bounds__(256) void k_scan1() {
    int b = blockIdx.x, t = threadIdx.x;
    int lane = t & 31, wid = t >> 5;
    int base = b * 1024 + t * 4;

    int v0 = 0, v1 = 0, v2 = 0, v3 = 0;
    if (base + 3 < NN) {
        int4 q = *(const int4*)&g_deg[base];
        v0 = q.x; v1 = q.y; v2 = q.z; v3 = q.w;
    }
    int s = v0 + v1 + v2 + v3;

    int inc = s;
#pragma unroll
    for (int o = 1; o < 32; o <<= 1) {
        int u = __shfl_up_sync(0xffffffffu, inc, o);
        if (lane >= o) inc += u;
    }
    __shared__ int ws[8];
    if (lane == 31) ws[wid] = inc;
    __syncthreads();
    int wpre = 0;
#pragma unroll
    for (int w = 0; w < 8; w++) wpre += (w < wid) ? ws[w] : 0;

    int ex = wpre + inc - s;
    if (base + 3 < NN) {
        int4 o;
        o.x = ex;
        o.y = ex + v0;
        o.z = ex + v0 + v1;
        o.w = ex + v0 + v1 + v2;
        *(int4*)&g_off[base] = o;
    }
    if (t == 255) g_bsum[b] = ex + s;
}

__global__ void k_scan2() {
    int t = threadIdx.x;
    int lane = t & 31, wid = t >> 5;
    int v = (t < SCAN_BLKS) ? g_bsum[t] : 0;
    int inc = v;
#pragma unroll
    for (int o = 1; o < 32; o <<= 1) {
        int u = __shfl_up_sync(0xffffffffu, inc, o);
        if (lane >= o) inc += u;
    }
    __shared__ int w0tot;
    if (wid == 0 && lane == 31) w0tot = inc;
    __syncthreads();
    int ex = inc - v + (wid ? w0tot : 0);
    if (t < SCAN_BLKS) g_bpre[t] = ex;
    if (t == SCAN_BLKS - 1) g_off[NN] = ex + v;
}

__global__ __launch_bounds__(256) void k_scan3() {
    int b = blockIdx.x, t = threadIdx.x;
    int base = b * 1024 + t * 4;
    int p = g_bpre[b];
    if (base + 3 < NN) {
        int4 o = *(const int4*)&g_off[base];
        o.x += p; o.y += p; o.z += p; o.w += p;
        *(int4*)&g_off[base] = o;
        *(int4*)&g_cur[base] = o;
    }
}

__global__ void k_scatter(const int* __restrict__ ei) {
    int e = blockIdx.x * blockDim.x + threadIdx.x;
    if (e < NE) {
        unsigned s = (unsigned)ei[e];
        unsigned d = (unsigned)ei[NE + e];
        if (s < NN && d < NN) {
            int p = atomicAdd(&g_cur[s], 1);
            if (p >= 0 && p < NE) g_dst[p] = (int)d;
        }
    }
}

// ---------------- WMMA GEMM: Wh = x@W + b, bf16 2-way split ----------------
__device__ __forceinline__ uint32_t pack_hi(float a, float b,
                                            __nv_bfloat16& ha, __nv_bfloat16& hb) {
    ha = __float2bfloat16(a);
    hb = __float2bfloat16(b);
    return (uint32_t)__bfloat16_as_ushort(ha) |
           ((uint32_t)__bfloat16_as_ushort(hb) << 16);
}
__device__ __forceinline__ uint32_t pack_lo(float a, float b,
                                            __nv_bfloat16 ha, __nv_bfloat16 hb) {
    __nv_bfloat16 la = __float2bfloat16(a - __bfloat162float(ha));
    __nv_bfloat16 lb = __float2bfloat16(b - __bfloat162float(hb));
    return (uint32_t)__bfloat16_as_ushort(la) |
           ((uint32_t)__bfloat16_as_ushort(lb) << 16);
}

__global__ __launch_bounds__(256) void k_wmma(const float* __restrict__ x,
                                              const float* __restrict__ W,
                                              const float* __restrict__ bias,
                                              const float* __restrict__ av) {
    extern __shared__ char smem[];
    __nv_bfloat16* xs_h = (__nv_bfloat16*)smem;                 // [64][48]
    __nv_bfloat16* xs_l = xs_h + BM * XS_LD;                    // +6144 B
    __nv_bfloat16* ws_h = (__nv_bfloat16*)(smem + 12288);       // [32][272]
    __nv_bfloat16* ws_l = ws_h + 32 * WS_LD;                    // +17408 B
    float* accs = (float*)smem;                                 // reused: [64][264]
    __shared__ float cb[256], ca[256];

    int tid = threadIdx.x;
    int w = tid >> 5;
    int wr = w & 3;    // warp row: rows wr*16..wr*16+15
    int wc = w >> 2;   // warp col: cols wc*128..wc*128+127
    int row0 = blockIdx.x * BM;

    cb[tid] = bias[tid];
    ca[tid] = av[tid];

    wmma::fragment<wmma::accumulator, 16, 16, 16, float> acc[8];
#pragma unroll
    for (int i = 0; i < 8; i++) wmma::fill_fragment(acc[i], 0.0f);

    for (int k0 = 0; k0 < IND; k0 += 32) {
        // ---- x tile: 64 rows x 32 k, fp32 -> bf16 hi/lo ----
        {
            int r = tid >> 2;
            int kk = (tid & 3) * 8;
            int grow = row0 + r;
            float4 v0 = make_float4(0.f, 0.f, 0.f, 0.f);
            float4 v1 = make_float4(0.f, 0.f, 0.f, 0.f);
            if (grow < NN) {
                v0 = *(const float4*)&x[grow * IND + k0 + kk];
                v1 = *(const float4*)&x[grow * IND + k0 + kk + 4];
            }
            __nv_bfloat16 h0, h1, h2, h3, h4, h5, h6, h7;
            uint4 hv, lv;
            hv.x = pack_hi(v0.x, v0.y, h0, h1);
            hv.y = pack_hi(v0.z, v0.w, h2, h3);
            hv.z = pack_hi(v1.x, v1.y, h4, h5);
            hv.w = pack_hi(v1.z, v1.w, h6, h7);
            lv.x = pack_lo(v0.x, v0.y, h0, h1);
            lv.y = pack_lo(v0.z, v0.w, h2, h3);
            lv.z = pack_lo(v1.x, v1.y, h4, h5);
            lv.w = pack_lo(v1.z, v1.w, h6, h7);
            *(uint4*)&xs_h[r * XS_LD + kk] = hv;
            *(uint4*)&xs_l[r * XS_LD + kk] = lv;
        }
        // ---- W tile: 32 k x 256 n, fp32 -> bf16 hi/lo ----
        {
            int kk = tid >> 3;
            int c0 = (tid & 7) * 32;
            const float4* wrow = (const float4*)&W[(k0 + kk) * FDIM + c0];
#pragma unroll
            for (int j = 0; j < 8; j++) {
                float4 v = wrow[j];
                __nv_bfloat16 h0, h1, h2, h3;
                uint2 hv, lv;
                hv.x = pack_hi(v.x, v.y, h0, h1);
                hv.y = pack_hi(v.z, v.w, h2, h3);
                lv.x = pack_lo(v.x, v.y, h0, h1);
                lv.y = pack_lo(v.z, v.w, h2, h3);
                *(uint2*)&ws_h[kk * WS_LD + c0 + j * 4] = hv;
                *(uint2*)&ws_l[kk * WS_LD + c0 + j * 4] = lv;
            }
        }
        __syncthreads();

#pragma unroll
        for (int kk = 0; kk < 32; kk += 16) {
            wmma::fragment<wmma::matrix_a, 16, 16, 16, __nv_bfloat16, wmma::row_major> ah, al;
            wmma::load_matrix_sync(ah, xs_h + wr * 16 * XS_LD + kk, XS_LD);
            wmma::load_matrix_sync(al, xs_l + wr * 16 * XS_LD + kk, XS_LD);
#pragma unroll
            for (int nt = 0; nt < 8; nt++) {
                wmma::fragment<wmma::matrix_b, 16, 16, 16, __nv_bfloat16, wmma::row_major> bh, bl;
                const __nv_bfloat16* bph = ws_h + kk * WS_LD + wc * 128 + nt * 16;
                const __nv_bfloat16* bpl = ws_l + kk * WS_LD + wc * 128 + nt * 16;
                wmma::load_matrix_sync(bh, bph, WS_LD);
                wmma::load_matrix_sync(bl, bpl, WS_LD);
                wmma::mma_sync(acc[nt], ah, bh, acc[nt]);
                wmma::mma_sync(acc[nt], ah, bl, acc[nt]);
                wmma::mma_sync(acc[nt], al, bh, acc[nt]);
            }
        }
        __syncthreads();
    }

    // ---- spill accumulators to smem (aliases mainloop tiles, post-sync) ----
#pragma unroll
    for (int nt = 0; nt < 8; nt++) {
        wmma::store_matrix_sync(accs + wr * 16 * ACC_LD + wc * 128 + nt * 16,
                                acc[nt], ACC_LD, wmma::mem_row_major);
    }
    __syncthreads();

    // ---- epilogue: 4 threads/row, bias + s/t dots + Wh store ----
    {
        int r = tid >> 2;
        int q = tid & 3;                 // column quarter (64 cols)
        int grow = row0 + r;
        const float* arow = accs + r * ACC_LD + q * 64;
        float ps = 0.f, pt = 0.f;
#pragma unroll
        for (int i = 0; i < 16; i++) {
            float4 f = *(const float4*)(arow + i * 4);
            int c = q * 64 + i * 4;
            f.x += cb[c];  f.y += cb[c + 1];  f.z += cb[c + 2];  f.w += cb[c + 3];
            int d = c & 127;
            ps += f.x * ca[d] + f.y * ca[d + 1] + f.z * ca[d + 2] + f.w * ca[d + 3];
            pt += f.x * ca[128 + d] + f.y * ca[129 + d] +
                  f.z * ca[130 + d] + f.w * ca[131 + d];
            if (grow < NN) *(float4*)&g_Wh[grow * FDIM + c] = f;
        }
        ps += __shfl_xor_sync(0xffffffffu, ps, 1);
        pt += __shfl_xor_sync(0xffffffffu, pt, 1);
        if (grow < NN) {
            if (q == 0) { g_s[grow * 2 + 0] = ps;  g_t[grow * 2 + 0] = pt; }
            if (q == 2) { g_s[grow * 2 + 1] = ps;  g_t[grow * 2 + 1] = pt; }
        }
    }
}

// ---------------- per-node online softmax + aggregation (1 warp / node) ----
__global__ __launch_bounds__(512) void k_agg(float* __restrict__ out) {
    int gwarp = (blockIdx.x * blockDim.x + threadIdx.x) >> 5;
    int lane  = threadIdx.x & 31;
    if (gwarp >= NN) return;
    int n = gwarp;
    int start = g_off[n];
    int end   = g_off[n + 1];

    const float4* wh4  = (const float4*)g_Wh;
    float4*       out4 = (float4*)out;

    if (end == start) {  // deg == 0 -> h' = Wh
        out4[n * 64 + lane]      = wh4[n * 64 + lane];
        out4[n * 64 + 32 + lane] = wh4[n * 64 + 32 + lane];
        return;
    }

    float2 ss = *(const float2*)&g_s[n * 2];
    float m0 = -INFINITY, m1 = -INFINITY;
    float d0 = 0.f, d1 = 0.f;
    float4 a0 = make_float4(0.f, 0.f, 0.f, 0.f);
    float4 a1 = make_float4(0.f, 0.f, 0.f, 0.f);

    int dnext = g_dst[start];
    for (int i = start; i < end; i++) {
        int dd = dnext;
        if (i + 1 < end) dnext = g_dst[i + 1];

        float2 tt = *(const float2*)&g_t[dd * 2];
        float e0 = ss.x + tt.x; e0 = (e0 > 0.f) ? e0 : 0.2f * e0;
        float e1 = ss.y + tt.y; e1 = (e1 > 0.f) ? e1 : 0.2f * e1;

        float nm0 = fmaxf(m0, e0), nm1 = fmaxf(m1, e1);
        float c0 = __expf(m0 - nm0), c1 = __expf(m1 - nm1);
        float w0 = __expf(e0 - nm0), w1 = __expf(e1 - nm1);
        d0 = d0 * c0 + w0;  m0 = nm0;
        d1 = d1 * c1 + w1;  m1 = nm1;

        float4 v0 = wh4[dd * 64 + lane];
        float4 v1 = wh4[dd * 64 + 32 + lane];
        a0.x = a0.x * c0 + w0 * v0.x;  a0.y = a0.y * c0 + w0 * v0.y;
        a0.z = a0.z * c0 + w0 * v0.z;  a0.w = a0.w * c0 + w0 * v0.w;
        a1.x = a1.x * c1 + w1 * v1.x;  a1.y = a1.y * c1 + w1 * v1.y;
        a1.z = a1.z * c1 + w1 * v1.z;  a1.w = a1.w * c1 + w1 * v1.w;
    }

    float i0 = 1.f / d0;
    float i1 = 1.f / d1;
    out4[n * 64 + lane]      = make_float4(a0.x * i0, a0.y * i0, a0.z * i0, a0.w * i0);
    out4[n * 64 + 32 + lane] = make_float4(a1.x * i1, a1.y * i1, a1.z * i1, a1.w * i1);
}

// ---------------- launch (fork-join: CSR build overlaps GEMM) --------------
static cudaStream_t g_s1 = 0;
static cudaEvent_t  g_evFork = 0, g_evJoin = 0;

extern "C" void kernel_launch(void* const* d_in, const int* in_sizes, int n_in,
                              void* d_out, int out_size) {
    const float* x  = (const float*)d_in[0];
    const int*   ei = (const int*)d_in[1];     // int32: JAX x64-disabled
    const float* W  = (const float*)d_in[2];
    const float* b  = (const float*)d_in[3];
    const float* a  = (const float*)d_in[4];
    float*       out = (float*)d_out;

    if (g_s1 == 0) {   // one-time resource setup (first call is eager, pre-capture)
        cudaStreamCreateWithFlags(&g_s1, cudaStreamNonBlocking);
        cudaEventCreateWithFlags(&g_evFork, cudaEventDisableTiming);
        cudaEventCreateWithFlags(&g_evJoin, cudaEventDisableTiming);
        cudaFuncSetAttribute(k_wmma, cudaFuncAttributeMaxDynamicSharedMemorySize,
                             SMEM_DYN);
    }

    // fork: CSR chain on s1, independent of GEMM
    cudaEventRecord(g_evFork, 0);
    cudaStreamWaitEvent(g_s1, g_evFork, 0);

    k_zero<<<(NN + 255) / 256, 256, 0, g_s1>>>();
    k_count<<<(NE + 255) / 256, 256, 0, g_s1>>>(ei);
    k_scan1<<<SCAN_BLKS, 256, 0, g_s1>>>();
    k_scan2<<<1, 64, 0, g_s1>>>();
    k_scan3<<<SCAN_BLKS, 256, 0, g_s1>>>();
    k_scatter<<<(NE + 255) / 256, 256, 0, g_s1>>>(ei);
    cudaEventRecord(g_evJoin, g_s1);

    // WMMA GEMM on the main stream, concurrent with the CSR chain
    k_wmma<<<GEMM_BLKS, 256, SMEM_DYN>>>(x, W, b, a);

    // join, then aggregate
    cudaStreamWaitEvent(0, g_evJoin, 0);
    k_agg<<<(NN * 32 + 511) / 512, 512>>>(out);
}

// round 9
// speedup vs baseline: 1.0803x; 1.0803x over previous
#include <cuda_runtime.h>
#include <cuda_bf16.h>
#include <mma.h>
#include <cstdint>
#include <math.h>

using namespace nvcuda;

#define NN 50000
#define NE 800000
#define IND 256
#define FDIM 256       // 2 heads * 128
#define SCAN_BLKS 49   // ceil(NN / 1024)
#define BM 64
#define GEMM_BLKS 782  // ceil(NN / 64)
#define XS_LD 48       // bf16 elems per xs row
#define WS_LD 272      // bf16 elems per ws row
#define ACC_LD 264     // fp32 elems per accs row
#define SMEM_DYN 67584 // max(47104 mainloop, 64*264*4 epilogue)
#define NX (NN * IND)  // 12.8M

// ---------------- scratch (static __device__, no allocation) ----------------
__device__ float g_Wh[NN * FDIM];   // 51.2 MB
__device__ float g_s[NN * 2];
__device__ float g_t[NN * 2];
__device__ __align__(16) __nv_bfloat16 g_xh[NX];
__device__ __align__(16) __nv_bfloat16 g_xl[NX];
__device__ __align__(16) __nv_bfloat16 g_wh_[IND * FDIM];
__device__ __align__(16) __nv_bfloat16 g_wl_[IND * FDIM];
__device__ __align__(16) int g_deg[NN];
__device__ __align__(16) int g_off[NN + 4];
__device__ __align__(16) int g_cur[NN];
__device__ int g_dst[NE];
__device__ int g_bsum[64];
__device__ int g_bpre[64];

// ---------------- bf16 hi/lo pack helpers ----------------
__device__ __forceinline__ uint32_t pack_hi(float a, float b,
                                            __nv_bfloat16& ha, __nv_bfloat16& hb) {
    ha = __float2bfloat16(a);
    hb = __float2bfloat16(b);
    return (uint32_t)__bfloat16_as_ushort(ha) |
           ((uint32_t)__bfloat16_as_ushort(hb) << 16);
}
__device__ __forceinline__ uint32_t pack_lo(float a, float b,
                                            __nv_bfloat16 ha, __nv_bfloat16 hb) {
    __nv_bfloat16 la = __float2bfloat16(a - __bfloat162float(ha));
    __nv_bfloat16 lb = __float2bfloat16(b - __bfloat162float(hb));
    return (uint32_t)__bfloat16_as_ushort(la) |
           ((uint32_t)__bfloat16_as_ushort(lb) << 16);
}

// ---------------- conversion kernels (once per launch) ----------------
__global__ __launch_bounds__(256) void k_conv_x(const float* __restrict__ x) {
    int i = (blockIdx.x * 256 + threadIdx.x) * 8;   // NX % 8 == 0
    if (i >= NX) return;
    float4 v0 = *(const float4*)&x[i];
    float4 v1 = *(const float4*)&x[i + 4];
    __nv_bfloat16 h0, h1, h2, h3, h4, h5, h6, h7;
    uint4 hv, lv;
    hv.x = pack_hi(v0.x, v0.y, h0, h1);
    hv.y = pack_hi(v0.z, v0.w, h2, h3);
    hv.z = pack_hi(v1.x, v1.y, h4, h5);
    hv.w = pack_hi(v1.z, v1.w, h6, h7);
    lv.x = pack_lo(v0.x, v0.y, h0, h1);
    lv.y = pack_lo(v0.z, v0.w, h2, h3);
    lv.z = pack_lo(v1.x, v1.y, h4, h5);
    lv.w = pack_lo(v1.z, v1.w, h6, h7);
    *(uint4*)&g_xh[i] = hv;
    *(uint4*)&g_xl[i] = lv;
}

__global__ __launch_bounds__(256) void k_conv_w(const float* __restrict__ W) {
    int i = (blockIdx.x * 256 + threadIdx.x) * 8;
    if (i >= IND * FDIM) return;
    float4 v0 = *(const float4*)&W[i];
    float4 v1 = *(const float4*)&W[i + 4];
    __nv_bfloat16 h0, h1, h2, h3, h4, h5, h6, h7;
    uint4 hv, lv;
    hv.x = pack_hi(v0.x, v0.y, h0, h1);
    hv.y = pack_hi(v0.z, v0.w, h2, h3);
    hv.z = pack_hi(v1.x, v1.y, h4, h5);
    hv.w = pack_hi(v1.z, v1.w, h6, h7);
    lv.x = pack_lo(v0.x, v0.y, h0, h1);
    lv.y = pack_lo(v0.z, v0.w, h2, h3);
    lv.z = pack_lo(v1.x, v1.y, h4, h5);
    lv.w = pack_lo(v1.z, v1.w, h6, h7);
    *(uint4*)&g_wh_[i] = hv;
    *(uint4*)&g_wl_[i] = lv;
}

// ---------------- CSR build ----------------
__global__ void k_zero() {
    int i = blockIdx.x * blockDim.x + threadIdx.x;
    if (i < NN) g_deg[i] = 0;
}

__global__ void k_count(const int* __restrict__ ei) {
    int e = blockIdx.x * blockDim.x + threadIdx.x;
    if (e < NE) {
        unsigned s = (unsigned)ei[e];
        if (s < NN) atomicAdd(&g_deg[s], 1);
    }
}

__global__ __launch_bounds__(256) void k_scan1() {
    int b = blockIdx.x, t = threadIdx.x;
    int lane = t & 31, wid = t >> 5;
    int base = b * 1024 + t * 4;

    int v0 = 0, v1 = 0, v2 = 0, v3 = 0;
    if (base + 3 < NN) {
        int4 q = *(const int4*)&g_deg[base];
        v0 = q.x; v1 = q.y; v2 = q.z; v3 = q.w;
    }
    int s = v0 + v1 + v2 + v3;

    int inc = s;
#pragma unroll
    for (int o = 1; o < 32; o <<= 1) {
        int u = __shfl_up_sync(0xffffffffu, inc, o);
        if (lane >= o) inc += u;
    }
    __shared__ int ws[8];
    if (lane == 31) ws[wid] = inc;
    __syncthreads();
    int wpre = 0;
#pragma unroll
    for (int w = 0; w < 8; w++) wpre += (w < wid) ? ws[w] : 0;

    int ex = wpre + inc - s;
    if (base + 3 < NN) {
        int4 o;
        o.x = ex;
        o.y = ex + v0;
        o.z = ex + v0 + v1;
        o.w = ex + v0 + v1 + v2;
        *(int4*)&g_off[base] = o;
    }
    if (t == 255) g_bsum[b] = ex + s;
}

__global__ void k_scan2() {
    int t = threadIdx.x;
    int lane = t & 31, wid = t >> 5;
    int v = (t < SCAN_BLKS) ? g_bsum[t] : 0;
    int inc = v;
#pragma unroll
    for (int o = 1; o < 32; o <<= 1) {
        int u = __shfl_up_sync(0xffffffffu, inc, o);
        if (lane >= o) inc += u;
    }
    __shared__ int w0tot;
    if (wid == 0 && lane == 31) w0tot = inc;
    __syncthreads();
    int ex = inc - v + (wid ? w0tot : 0);
    if (t < SCAN_BLKS) g_bpre[t] = ex;
    if (t == SCAN_BLKS - 1) g_off[NN] = ex + v;
}

__global__ __launch_bounds__(256) void k_scan3() {
    int b = blockIdx.x, t = threadIdx.x;
    int base = b * 1024 + t * 4;
    int p = g_bpre[b];
    if (base + 3 < NN) {
        int4 o = *(const int4*)&g_off[base];
        o.x += p; o.y += p; o.z += p; o.w += p;
        *(int4*)&g_off[base] = o;
        *(int4*)&g_cur[base] = o;
    }
}

__global__ void k_scatter(const int* __restrict__ ei) {
    int e = blockIdx.x * blockDim.x + threadIdx.x;
    if (e < NE) {
        unsigned s = (unsigned)ei[e];
        unsigned d = (unsigned)ei[NE + e];
        if (s < NN && d < NN) {
            int p = atomicAdd(&g_cur[s], 1);
            if (p >= 0 && p < NE) g_dst[p] = (int)d;
        }
    }
}

// ---------------- WMMA GEMM: pre-converted bf16, copy-only staging ---------
__global__ __launch_bounds__(256) void k_wmma(const float* __restrict__ bias,
                                              const float* __restrict__ av) {
    extern __shared__ char smem[];
    __nv_bfloat16* xs_h = (__nv_bfloat16*)smem;                 // [64][48]
    __nv_bfloat16* xs_l = xs_h + BM * XS_LD;
    __nv_bfloat16* ws_h = (__nv_bfloat16*)(smem + 12288);       // [32][272]
    __nv_bfloat16* ws_l = ws_h + 32 * WS_LD;
    float* accs = (float*)smem;                                 // reused post-loop
    __shared__ float cb[256], ca[256];

    int tid = threadIdx.x;
    int w = tid >> 5;
    int wr = w & 3;    // warp row: rows wr*16..wr*16+15
    int wc = w >> 2;   // warp col: cols wc*128..wc*128+127
    int row0 = blockIdx.x * BM;

    cb[tid] = bias[tid];
    ca[tid] = av[tid];

    wmma::fragment<wmma::accumulator, 16, 16, 16, float> acc[8];
#pragma unroll
    for (int i = 0; i < 8; i++) wmma::fill_fragment(acc[i], 0.0f);

    for (int k0 = 0; k0 < IND; k0 += 32) {
        // ---- x tiles: copy 64x32 bf16 (hi+lo), uint4 moves ----
        {
            int r = tid >> 2;                 // 0..63
            int kk = (tid & 3) * 8;           // 0,8,16,24
            int grow = row0 + r;
            uint4 hv = make_uint4(0, 0, 0, 0), lv = make_uint4(0, 0, 0, 0);
            if (grow < NN) {
                hv = *(const uint4*)&g_xh[grow * IND + k0 + kk];
                lv = *(const uint4*)&g_xl[grow * IND + k0 + kk];
            }
            *(uint4*)&xs_h[r * XS_LD + kk] = hv;
            *(uint4*)&xs_l[r * XS_LD + kk] = lv;
        }
        // ---- W tiles: copy 32x256 bf16 (hi+lo) ----
        {
            int kk = tid >> 3;                // 0..31
            int c0 = (tid & 7) * 32;          // 0..224
#pragma unroll
            for (int j = 0; j < 4; j++) {
                *(uint4*)&ws_h[kk * WS_LD + c0 + j * 8] =
                    *(const uint4*)&g_wh_[(k0 + kk) * FDIM + c0 + j * 8];
                *(uint4*)&ws_l[kk * WS_LD + c0 + j * 8] =
                    *(const uint4*)&g_wl_[(k0 + kk) * FDIM + c0 + j * 8];
            }
        }
        __syncthreads();

#pragma unroll
        for (int kk = 0; kk < 32; kk += 16) {
            wmma::fragment<wmma::matrix_a, 16, 16, 16, __nv_bfloat16, wmma::row_major> ah, al;
            wmma::load_matrix_sync(ah, xs_h + wr * 16 * XS_LD + kk, XS_LD);
            wmma::load_matrix_sync(al, xs_l + wr * 16 * XS_LD + kk, XS_LD);
#pragma unroll
            for (int nt = 0; nt < 8; nt++) {
                wmma::fragment<wmma::matrix_b, 16, 16, 16, __nv_bfloat16, wmma::row_major> bh, bl;
                wmma::load_matrix_sync(bh, ws_h + kk * WS_LD + wc * 128 + nt * 16, WS_LD);
                wmma::load_matrix_sync(bl, ws_l + kk * WS_LD + wc * 128 + nt * 16, WS_LD);
                wmma::mma_sync(acc[nt], ah, bh, acc[nt]);
                wmma::mma_sync(acc[nt], ah, bl, acc[nt]);
                wmma::mma_sync(acc[nt], al, bh, acc[nt]);
            }
        }
        __syncthreads();
    }

    // ---- spill accumulators to smem (aliases mainloop tiles, post-sync) ----
#pragma unroll
    for (int nt = 0; nt < 8; nt++) {
        wmma::store_matrix_sync(accs + wr * 16 * ACC_LD + wc * 128 + nt * 16,
                                acc[nt], ACC_LD, wmma::mem_row_major);
    }
    __syncthreads();

    // ---- epilogue: 4 threads/row, bias + s/t dots + Wh store ----
    {
        int r = tid >> 2;
        int q = tid & 3;
        int grow = row0 + r;
        const float* arow = accs + r * ACC_LD + q * 64;
        float ps = 0.f, pt = 0.f;
#pragma unroll
        for (int i = 0; i < 16; i++) {
            float4 f = *(const float4*)(arow + i * 4);
            int c = q * 64 + i * 4;
            f.x += cb[c];  f.y += cb[c + 1];  f.z += cb[c + 2];  f.w += cb[c + 3];
            int d = c & 127;
            ps += f.x * ca[d] + f.y * ca[d + 1] + f.z * ca[d + 2] + f.w * ca[d + 3];
            pt += f.x * ca[128 + d] + f.y * ca[129 + d] +
                  f.z * ca[130 + d] + f.w * ca[131 + d];
            if (grow < NN) *(float4*)&g_Wh[grow * FDIM + c] = f;
        }
        ps += __shfl_xor_sync(0xffffffffu, ps, 1);
        pt += __shfl_xor_sync(0xffffffffu, pt, 1);
        if (grow < NN) {
            if (q == 0) { g_s[grow * 2 + 0] = ps;  g_t[grow * 2 + 0] = pt; }
            if (q == 2) { g_s[grow * 2 + 1] = ps;  g_t[grow * 2 + 1] = pt; }
        }
    }
}

// ---------------- per-node online softmax + aggregation (1 warp / node) ----
__global__ __launch_bounds__(512) void k_agg(float* __restrict__ out) {
    int gwarp = (blockIdx.x * blockDim.x + threadIdx.x) >> 5;
    int lane  = threadIdx.x & 31;
    if (gwarp >= NN) return;
    int n = gwarp;
    int start = g_off[n];
    int end   = g_off[n + 1];

    const float4* wh4  = (const float4*)g_Wh;
    float4*       out4 = (float4*)out;

    if (end == start) {  // deg == 0 -> h' = Wh
        out4[n * 64 + lane]      = wh4[n * 64 + lane];
        out4[n * 64 + 32 + lane] = wh4[n * 64 + 32 + lane];
        return;
    }

    float2 ss = *(const float2*)&g_s[n * 2];
    float m0 = -INFINITY, m1 = -INFINITY;
    float d0 = 0.f, d1 = 0.f;
    float4 a0 = make_float4(0.f, 0.f, 0.f, 0.f);
    float4 a1 = make_float4(0.f, 0.f, 0.f, 0.f);

    int dnext = g_dst[start];
    for (int i = start; i < end; i++) {
        int dd = dnext;
        if (i + 1 < end) dnext = g_dst[i + 1];

        float2 tt = *(const float2*)&g_t[dd * 2];
        float e0 = ss.x + tt.x; e0 = (e0 > 0.f) ? e0 : 0.2f * e0;
        float e1 = ss.y + tt.y; e1 = (e1 > 0.f) ? e1 : 0.2f * e1;

        float nm0 = fmaxf(m0, e0), nm1 = fmaxf(m1, e1);
        float c0 = __expf(m0 - nm0), c1 = __expf(m1 - nm1);
        float w0 = __expf(e0 - nm0), w1 = __expf(e1 - nm1);
        d0 = d0 * c0 + w0;  m0 = nm0;
        d1 = d1 * c1 + w1;  m1 = nm1;

        float4 v0 = wh4[dd * 64 + lane];
        float4 v1 = wh4[dd * 64 + 32 + lane];
        a0.x = a0.x * c0 + w0 * v0.x;  a0.y = a0.y * c0 + w0 * v0.y;
        a0.z = a0.z * c0 + w0 * v0.z;  a0.w = a0.w * c0 + w0 * v0.w;
        a1.x = a1.x * c1 + w1 * v1.x;  a1.y = a1.y * c1 + w1 * v1.y;
        a1.z = a1.z * c1 + w1 * v1.z;  a1.w = a1.w * c1 + w1 * v1.w;
    }

    float i0 = 1.f / d0;
    float i1 = 1.f / d1;
    out4[n * 64 + lane]      = make_float4(a0.x * i0, a0.y * i0, a0.z * i0, a0.w * i0);
    out4[n * 64 + 32 + lane] = make_float4(a1.x * i1, a1.y * i1, a1.z * i1, a1.w * i1);
}

// ---------------- launch (fork-join: CSR build overlaps conv+GEMM) ---------
static cudaStream_t g_s1 = 0;
static cudaEvent_t  g_evFork = 0, g_evJoin = 0;

extern "C" void kernel_launch(void* const* d_in, const int* in_sizes, int n_in,
                              void* d_out, int out_size) {
    const float* x  = (const float*)d_in[0];
    const int*   ei = (const int*)d_in[1];     // int32: JAX x64-disabled
    const float* W  = (const float*)d_in[2];
    const float* b  = (const float*)d_in[3];
    const float* a  = (const float*)d_in[4];
    float*       out = (float*)d_out;

    if (g_s1 == 0) {   // one-time resource setup (first call is eager, pre-capture)
        cudaStreamCreateWithFlags(&g_s1, cudaStreamNonBlocking);
        cudaEventCreateWithFlags(&g_evFork, cudaEventDisableTiming);
        cudaEventCreateWithFlags(&g_evJoin, cudaEventDisableTiming);
        cudaFuncSetAttribute(k_wmma, cudaFuncAttributeMaxDynamicSharedMemorySize,
                             SMEM_DYN);
    }

    // fork: CSR chain on s1, independent of conv+GEMM
    cudaEventRecord(g_evFork, 0);
    cudaStreamWaitEvent(g_s1, g_evFork, 0);

    k_zero<<<(NN + 255) / 256, 256, 0, g_s1>>>();
    k_count<<<(NE + 255) / 256, 256, 0, g_s1>>>(ei);
    k_scan1<<<SCAN_BLKS, 256, 0, g_s1>>>();
    k_scan2<<<1, 64, 0, g_s1>>>();
    k_scan3<<<SCAN_BLKS, 256, 0, g_s1>>>();
    k_scatter<<<(NE + 255) / 256, 256, 0, g_s1>>>(ei);
    cudaEventRecord(g_evJoin, g_s1);

    // conversion then WMMA GEMM on the main stream
    k_conv_w<<<(IND * FDIM / 8 + 255) / 256, 256>>>(W);
    k_conv_x<<<(NX / 8 + 255) / 256, 256>>>(x);
    k_wmma<<<GEMM_BLKS, 256, SMEM_DYN>>>(b, a);

    // join, then aggregate
    cudaStreamWaitEvent(0, g_evJoin, 0);
    k_agg<<<(NN * 32 + 511) / 512, 512>>>(out);
}

// round 10
// speedup vs baseline: 1.4376x; 1.3307x over previous
#include <cuda_runtime.h>
#include <cstdint>
#include <math.h>

#define NN 50000
#define NE 800000
#define IND 256
#define FDIM 256       // 2 heads * 128
#define SCAN_BLKS 49   // ceil(NN / 1024)

// ---------------- scratch (static __device__, no allocation) ----------------
__device__ float g_Wh[NN * FDIM];   // 51.2 MB - fits L2
__device__ float g_s[NN * 2];
__device__ float g_t[NN * 2];
__device__ __align__(16) int g_deg[NN];
__device__ __align__(16) int g_off[NN + 4];
__device__ __align__(16) int g_cur[NN];
__device__ int g_dst[NE];
__device__ int g_bsum[64];
__device__ int g_bpre[64];

// ---------------- CSR build ----------------
__global__ void k_zero() {
    int i = blockIdx.x * blockDim.x + threadIdx.x;
    if (i < NN) g_deg[i] = 0;
}

__global__ void k_count(const int* __restrict__ ei) {
    int e = blockIdx.x * blockDim.x + threadIdx.x;
    if (e < NE) {
        unsigned s = (unsigned)ei[e];
        if (s < NN) atomicAdd(&g_deg[s], 1);
    }
}

__global__ __launch_bounds__(256) void k_scan1() {
    int b = blockIdx.x, t = threadIdx.x;
    int lane = t & 31, wid = t >> 5;
    int base = b * 1024 + t * 4;

    int v0 = 0, v1 = 0, v2 = 0, v3 = 0;
    if (base + 3 < NN) {
        int4 q = *(const int4*)&g_deg[base];
        v0 = q.x; v1 = q.y; v2 = q.z; v3 = q.w;
    }
    int s = v0 + v1 + v2 + v3;

    int inc = s;
#pragma unroll
    for (int o = 1; o < 32; o <<= 1) {
        int u = __shfl_up_sync(0xffffffffu, inc, o);
        if (lane >= o) inc += u;
    }
    __shared__ int ws[8];
    if (lane == 31) ws[wid] = inc;
    __syncthreads();
    int wpre = 0;
#pragma unroll
    for (int w = 0; w < 8; w++) wpre += (w < wid) ? ws[w] : 0;

    int ex = wpre + inc - s;
    if (base + 3 < NN) {
        int4 o;
        o.x = ex;
        o.y = ex + v0;
        o.z = ex + v0 + v1;
        o.w = ex + v0 + v1 + v2;
        *(int4*)&g_off[base] = o;
    }
    if (t == 255) g_bsum[b] = ex + s;
}

__global__ void k_scan2() {
    int t = threadIdx.x;
    int lane = t & 31, wid = t >> 5;
    int v = (t < SCAN_BLKS) ? g_bsum[t] : 0;
    int inc = v;
#pragma unroll
    for (int o = 1; o < 32; o <<= 1) {
        int u = __shfl_up_sync(0xffffffffu, inc, o);
        if (lane >= o) inc += u;
    }
    __shared__ int w0tot;
    if (wid == 0 && lane == 31) w0tot = inc;
    __syncthreads();
    int ex = inc - v + (wid ? w0tot : 0);
    if (t < SCAN_BLKS) g_bpre[t] = ex;
    if (t == SCAN_BLKS - 1) g_off[NN] = ex + v;
}

__global__ __launch_bounds__(256) void k_scan3() {
    int b = blockIdx.x, t = threadIdx.x;
    int base = b * 1024 + t * 4;
    int p = g_bpre[b];
    if (base + 3 < NN) {
        int4 o = *(const int4*)&g_off[base];
        o.x += p; o.y += p; o.z += p; o.w += p;
        *(int4*)&g_off[base] = o;
        *(int4*)&g_cur[base] = o;
    }
}

__global__ void k_scatter(const int* __restrict__ ei) {
    int e = blockIdx.x * blockDim.x + threadIdx.x;
    if (e < NE) {
        unsigned s = (unsigned)ei[e];
        unsigned d = (unsigned)ei[NE + e];
        if (s < NN && d < NN) {
            int p = atomicAdd(&g_cur[s], 1);
            if (p >= 0 && p < NE) g_dst[p] = (int)d;
        }
    }
}

// ---------------- GEMM: Wh = x @ W + b, fused s/t epilogue ----------------
// BM=64, BN=128 (one head per blockIdx.y), BK=32, 256 threads, f32x2 packed FMA.
__global__ __launch_bounds__(256) void k_gemm(const float* __restrict__ x,
                                              const float* __restrict__ W,
                                              const float* __restrict__ b,
                                              const float* __restrict__ a) {
    __shared__ float xs[32][65];   // xs[k][row], padded
    __shared__ float ws[32][128];  // ws[k][n]

    int tid  = threadIdx.x;
    int h    = blockIdx.y;                 // head / 128-col tile
    int row0 = blockIdx.x * 64;
    int tr   = tid >> 5;                   // warp id: rows tr*8 .. tr*8+7
    int tc   = tid & 31;                   // cols tc*4 .. tc*4+3 (within head)

    unsigned long long acc2[8][2];
    unsigned long long zz;
    asm("mov.b64 %0, {%1, %1};" : "=l"(zz) : "r"(0u));
#pragma unroll
    for (int i = 0; i < 8; i++) { acc2[i][0] = zz; acc2[i][1] = zz; }

    for (int k0 = 0; k0 < IND; k0 += 32) {
        // load x tile (64 rows x 32 k), transposed into xs[k][row]
#pragma unroll
        for (int q = 0; q < 2; q++) {
            int idx  = tid * 2 + q;
            int r    = idx >> 3;
            int kq   = (idx & 7) << 2;
            int grow = row0 + r;
            float4 xv = make_float4(0.f, 0.f, 0.f, 0.f);
            if (grow < NN) xv = *(const float4*)&x[grow * IND + k0 + kq];
            xs[kq + 0][r] = xv.x;
            xs[kq + 1][r] = xv.y;
            xs[kq + 2][r] = xv.z;
            xs[kq + 3][r] = xv.w;
        }
        // load W tile (32 k x 128 n)
        {
            int kr = tid >> 5;
            int nq = (tid & 31) << 2;
#pragma unroll
            for (int p = 0; p < 4; p++) {
                int k = kr + p * 8;
                *(float4*)&ws[k][nq] = *(const float4*)&W[(k0 + k) * FDIM + h * 128 + nq];
            }
        }
        __syncthreads();
#pragma unroll
        for (int kk = 0; kk < 32; kk++) {
            unsigned long long rn01 = *(const unsigned long long*)&ws[kk][tc * 4];
            unsigned long long rn23 = *(const unsigned long long*)&ws[kk][tc * 4 + 2];
#pragma unroll
            for (int i = 0; i < 8; i++) {
                float rm = xs[kk][tr * 8 + i];
                unsigned long long am;
                asm("mov.b64 %0, {%1, %1};" : "=l"(am) : "r"(__float_as_uint(rm)));
                asm("fma.rn.f32x2 %0, %1, %2, %3;"
                    : "=l"(acc2[i][0]) : "l"(am), "l"(rn01), "l"(acc2[i][0]));
                asm("fma.rn.f32x2 %0, %1, %2, %3;"
                    : "=l"(acc2[i][1]) : "l"(am), "l"(rn23), "l"(acc2[i][1]));
            }
        }
        __syncthreads();
    }

    // epilogue: bias, store Wh, fused s/t dot + warp reduce
    float4 bb = *(const float4*)&b[h * 128 + tc * 4];
    float as0 = a[tc * 4 + 0], as1 = a[tc * 4 + 1], as2 = a[tc * 4 + 2], as3 = a[tc * 4 + 3];
    float at0 = a[128 + tc * 4 + 0], at1 = a[128 + tc * 4 + 1];
    float at2 = a[128 + tc * 4 + 2], at3 = a[128 + tc * 4 + 3];

#pragma unroll
    for (int i = 0; i < 8; i++) {
        int grow = row0 + tr * 8 + i;
        unsigned int u0, u1, u2, u3;
        asm("mov.b64 {%0, %1}, %2;" : "=r"(u0), "=r"(u1) : "l"(acc2[i][0]));
        asm("mov.b64 {%0, %1}, %2;" : "=r"(u2), "=r"(u3) : "l"(acc2[i][1]));
        float f0 = __uint_as_float(u0) + bb.x;
        float f1 = __uint_as_float(u1) + bb.y;
        float f2 = __uint_as_float(u2) + bb.z;
        float f3 = __uint_as_float(u3) + bb.w;
        float ps = f0 * as0 + f1 * as1 + f2 * as2 + f3 * as3;
        float pt = f0 * at0 + f1 * at1 + f2 * at2 + f3 * at3;
#pragma unroll
        for (int off = 16; off > 0; off >>= 1) {
            ps += __shfl_down_sync(0xffffffffu, ps, off);
            pt += __shfl_down_sync(0xffffffffu, pt, off);
        }
        if (grow < NN) {
            *(float4*)&g_Wh[grow * FDIM + h * 128 + tc * 4] = make_float4(f0, f1, f2, f3);
            if (tc == 0) {
                g_s[grow * 2 + h] = ps;
                g_t[grow * 2 + h] = pt;
            }
        }
    }
}

// ---------------- per-node online softmax + aggregation (1 warp / node) ----
// 2-edge unrolled: both Wh rows in flight per iteration (2 KB MLP / warp).
__global__ __launch_bounds__(512) void k_agg(float* __restrict__ out) {
    int gwarp = (blockIdx.x * blockDim.x + threadIdx.x) >> 5;
    int lane  = threadIdx.x & 31;
    if (gwarp >= NN) return;
    int n = gwarp;
    int start = g_off[n];
    int end   = g_off[n + 1];

    const float4* __restrict__ wh4 = (const float4*)g_Wh;
    float4* out4 = (float4*)out;

    if (end == start) {  // deg == 0 -> h' = Wh
        out4[n * 64 + lane]      = wh4[n * 64 + lane];
        out4[n * 64 + 32 + lane] = wh4[n * 64 + 32 + lane];
        return;
    }

    float2 ss = *(const float2*)&g_s[n * 2];
    float m0 = -INFINITY, m1 = -INFINITY;
    float d0 = 0.f, d1 = 0.f;
    float4 a0 = make_float4(0.f, 0.f, 0.f, 0.f);
    float4 a1 = make_float4(0.f, 0.f, 0.f, 0.f);

    int i = start;
    for (; i + 1 < end; i += 2) {
        int dA = g_dst[i];
        int dB = g_dst[i + 1];
        float2 tA = *(const float2*)&g_t[dA * 2];
        float2 tB = *(const float2*)&g_t[dB * 2];
        // all four 512B row-halves issue before the exp chain
        float4 vA0 = wh4[dA * 64 + lane];
        float4 vA1 = wh4[dA * 64 + 32 + lane];
        float4 vB0 = wh4[dB * 64 + lane];
        float4 vB1 = wh4[dB * 64 + 32 + lane];

        float eA0 = ss.x + tA.x; eA0 = (eA0 > 0.f) ? eA0 : 0.2f * eA0;
        float eA1 = ss.y + tA.y; eA1 = (eA1 > 0.f) ? eA1 : 0.2f * eA1;
        float eB0 = ss.x + tB.x; eB0 = (eB0 > 0.f) ? eB0 : 0.2f * eB0;
        float eB1 = ss.y + tB.y; eB1 = (eB1 > 0.f) ? eB1 : 0.2f * eB1;

        float nm0 = fmaxf(m0, fmaxf(eA0, eB0));
        float nm1 = fmaxf(m1, fmaxf(eA1, eB1));
        float c0  = __expf(m0 - nm0),  c1  = __expf(m1 - nm1);
        float wA0 = __expf(eA0 - nm0), wA1 = __expf(eA1 - nm1);
        float wB0 = __expf(eB0 - nm0), wB1 = __expf(eB1 - nm1);
        d0 = d0 * c0 + wA0 + wB0;  m0 = nm0;
        d1 = d1 * c1 + wA1 + wB1;  m1 = nm1;

        a0.x = a0.x * c0 + wA0 * vA0.x + wB0 * vB0.x;
        a0.y = a0.y * c0 + wA0 * vA0.y + wB0 * vB0.y;
        a0.z = a0.z * c0 + wA0 * vA0.z + wB0 * vB0.z;
        a0.w = a0.w * c0 + wA0 * vA0.w + wB0 * vB0.w;
        a1.x = a1.x * c1 + wA1 * vA1.x + wB1 * vB1.x;
        a1.y = a1.y * c1 + wA1 * vA1.y + wB1 * vB1.y;
        a1.z = a1.z * c1 + wA1 * vA1.z + wB1 * vB1.z;
        a1.w = a1.w * c1 + wA1 * vA1.w + wB1 * vB1.w;
    }
    if (i < end) {   // odd tail
        int dd = g_dst[i];
        float2 tt = *(const float2*)&g_t[dd * 2];
        float4 v0 = wh4[dd * 64 + lane];
        float4 v1 = wh4[dd * 64 + 32 + lane];

        float e0 = ss.x + tt.x; e0 = (e0 > 0.f) ? e0 : 0.2f * e0;
        float e1 = ss.y + tt.y; e1 = (e1 > 0.f) ? e1 : 0.2f * e1;
        float nm0 = fmaxf(m0, e0), nm1 = fmaxf(m1, e1);
        float c0 = __expf(m0 - nm0), c1 = __expf(m1 - nm1);
        float w0 = __expf(e0 - nm0), w1 = __expf(e1 - nm1);
        d0 = d0 * c0 + w0;
        d1 = d1 * c1 + w1;
        a0.x = a0.x * c0 + w0 * v0.x;  a0.y = a0.y * c0 + w0 * v0.y;
        a0.z = a0.z * c0 + w0 * v0.z;  a0.w = a0.w * c0 + w0 * v0.w;
        a1.x = a1.x * c1 + w1 * v1.x;  a1.y = a1.y * c1 + w1 * v1.y;
        a1.z = a1.z * c1 + w1 * v1.z;  a1.w = a1.w * c1 + w1 * v1.w;
    }

    float i0 = 1.f / d0;
    float i1 = 1.f / d1;
    out4[n * 64 + lane]      = make_float4(a0.x * i0, a0.y * i0, a0.z * i0, a0.w * i0);
    out4[n * 64 + 32 + lane] = make_float4(a1.x * i1, a1.y * i1, a1.z * i1, a1.w * i1);
}

// ---------------- launch (fork-join: CSR build overlaps GEMM) --------------
static cudaStream_t g_s1 = 0;
static cudaEvent_t  g_evFork = 0, g_evJoin = 0;

extern "C" void kernel_launch(void* const* d_in, const int* in_sizes, int n_in,
                              void* d_out, int out_size) {
    const float* x  = (const float*)d_in[0];
    const int*   ei = (const int*)d_in[1];     // int32: JAX x64-disabled
    const float* W  = (const float*)d_in[2];
    const float* b  = (const float*)d_in[3];
    const float* a  = (const float*)d_in[4];
    float*       out = (float*)d_out;

    if (g_s1 == 0) {   // one-time resource setup (first call is eager, pre-capture)
        cudaStreamCreateWithFlags(&g_s1, cudaStreamNonBlocking);
        cudaEventCreateWithFlags(&g_evFork, cudaEventDisableTiming);
        cudaEventCreateWithFlags(&g_evJoin, cudaEventDisableTiming);
    }

    // fork: CSR chain on s1, independent of GEMM
    cudaEventRecord(g_evFork, 0);
    cudaStreamWaitEvent(g_s1, g_evFork, 0);

    k_zero<<<(NN + 255) / 256, 256, 0, g_s1>>>();
    k_count<<<(NE + 255) / 256, 256, 0, g_s1>>>(ei);
    k_scan1<<<SCAN_BLKS, 256, 0, g_s1>>>();
    k_scan2<<<1, 64, 0, g_s1>>>();
    k_scan3<<<SCAN_BLKS, 256, 0, g_s1>>>();
    k_scatter<<<(NE + 255) / 256, 256, 0, g_s1>>>(ei);
    cudaEventRecord(g_evJoin, g_s1);

    // GEMM on the main stream, concurrent with the CSR chain
    dim3 gg((NN + 63) / 64, 2);
    k_gemm<<<gg, 256>>>(x, W, b, a);

    // join, then aggregate
    cudaStreamWaitEvent(0, g_evJoin, 0);
    k_agg<<<(NN * 32 + 511) / 512, 512>>>(out);
}

// round 11
// speedup vs baseline: 1.4797x; 1.0293x over previous
#include <cuda_runtime.h>
#include <cuda_fp16.h>
#include <cstdint>
#include <math.h>

#define NN 50000
#define NE 800000
#define IND 256
#define FDIM 256       // 2 heads * 128
#define SCAN_BLKS 49   // ceil(NN / 1024)

// ---------------- scratch (static __device__, no allocation) ----------------
__device__ float g_Wh[NN * FDIM];            // 51.2 MB fp32 (deg==0 copy path)
__device__ __align__(16) __half g_Whh[NN * FDIM];   // 25.6 MB fp16 gather mirror
__device__ float g_s[NN * 2];
__device__ float g_t[NN * 2];
__device__ __align__(16) int g_deg[NN];
__device__ __align__(16) int g_off[NN + 4];
__device__ __align__(16) int g_cur[NN];
__device__ int g_dst[NE];
__device__ int g_bsum[64];
__device__ int g_bpre[64];

// ---------------- CSR build ----------------
__global__ void k_zero() {
    int i = blockIdx.x * blockDim.x + threadIdx.x;
    if (i < NN) g_deg[i] = 0;
}

__global__ void k_count(const int* __restrict__ ei) {
    int e = blockIdx.x * blockDim.x + threadIdx.x;
    if (e < NE) {
        unsigned s = (unsigned)ei[e];
        if (s < NN) atomicAdd(&g_deg[s], 1);
    }
}

__global__ __launch_bounds__(256) void k_scan1() {
    int b = blockIdx.x, t = threadIdx.x;
    int lane = t & 31, wid = t >> 5;
    int base = b * 1024 + t * 4;

    int v0 = 0, v1 = 0, v2 = 0, v3 = 0;
    if (base + 3 < NN) {
        int4 q = *(const int4*)&g_deg[base];
        v0 = q.x; v1 = q.y; v2 = q.z; v3 = q.w;
    }
    int s = v0 + v1 + v2 + v3;

    int inc = s;
#pragma unroll
    for (int o = 1; o < 32; o <<= 1) {
        int u = __shfl_up_sync(0xffffffffu, inc, o);
        if (lane >= o) inc += u;
    }
    __shared__ int ws[8];
    if (lane == 31) ws[wid] = inc;
    __syncthreads();
    int wpre = 0;
#pragma unroll
    for (int w = 0; w < 8; w++) wpre += (w < wid) ? ws[w] : 0;

    int ex = wpre + inc - s;
    if (base + 3 < NN) {
        int4 o;
        o.x = ex;
        o.y = ex + v0;
        o.z = ex + v0 + v1;
        o.w = ex + v0 + v1 + v2;
        *(int4*)&g_off[base] = o;
    }
    if (t == 255) g_bsum[b] = ex + s;
}

__global__ void k_scan2() {
    int t = threadIdx.x;
    int lane = t & 31, wid = t >> 5;
    int v = (t < SCAN_BLKS) ? g_bsum[t] : 0;
    int inc = v;
#pragma unroll
    for (int o = 1; o < 32; o <<= 1) {
        int u = __shfl_up_sync(0xffffffffu, inc, o);
        if (lane >= o) inc += u;
    }
    __shared__ int w0tot;
    if (wid == 0 && lane == 31) w0tot = inc;
    __syncthreads();
    int ex = inc - v + (wid ? w0tot : 0);
    if (t < SCAN_BLKS) g_bpre[t] = ex;
    if (t == SCAN_BLKS - 1) g_off[NN] = ex + v;
}

__global__ __launch_bounds__(256) void k_scan3() {
    int b = blockIdx.x, t = threadIdx.x;
    int base = b * 1024 + t * 4;
    int p = g_bpre[b];
    if (base + 3 < NN) {
        int4 o = *(const int4*)&g_off[base];
        o.x += p; o.y += p; o.z += p; o.w += p;
        *(int4*)&g_off[base] = o;
        *(int4*)&g_cur[base] = o;
    }
}

__global__ void k_scatter(const int* __restrict__ ei) {
    int e = blockIdx.x * blockDim.x + threadIdx.x;
    if (e < NE) {
        unsigned s = (unsigned)ei[e];
        unsigned d = (unsigned)ei[NE + e];
        if (s < NN && d < NN) {
            int p = atomicAdd(&g_cur[s], 1);
            if (p >= 0 && p < NE) g_dst[p] = (int)d;
        }
    }
}

// ---------------- GEMM: Wh = x @ W + b, fused s/t epilogue ----------------
__global__ __launch_bounds__(256) void k_gemm(const float* __restrict__ x,
                                              const float* __restrict__ W,
                                              const float* __restrict__ b,
                                              const float* __restrict__ a) {
    __shared__ float xs[32][65];   // xs[k][row], padded
    __shared__ float ws[32][128];  // ws[k][n]

    int tid  = threadIdx.x;
    int h    = blockIdx.y;                 // head / 128-col tile
    int row0 = blockIdx.x * 64;
    int tr   = tid >> 5;                   // warp id: rows tr*8 .. tr*8+7
    int tc   = tid & 31;                   // cols tc*4 .. tc*4+3 (within head)

    unsigned long long acc2[8][2];
    unsigned long long zz;
    asm("mov.b64 %0, {%1, %1};" : "=l"(zz) : "r"(0u));
#pragma unroll
    for (int i = 0; i < 8; i++) { acc2[i][0] = zz; acc2[i][1] = zz; }

    for (int k0 = 0; k0 < IND; k0 += 32) {
#pragma unroll
        for (int q = 0; q < 2; q++) {
            int idx  = tid * 2 + q;
            int r    = idx >> 3;
            int kq   = (idx & 7) << 2;
            int grow = row0 + r;
            float4 xv = make_float4(0.f, 0.f, 0.f, 0.f);
            if (grow < NN) xv = *(const float4*)&x[grow * IND + k0 + kq];
            xs[kq + 0][r] = xv.x;
            xs[kq + 1][r] = xv.y;
            xs[kq + 2][r] = xv.z;
            xs[kq + 3][r] = xv.w;
        }
        {
            int kr = tid >> 5;
            int nq = (tid & 31) << 2;
#pragma unroll
            for (int p = 0; p < 4; p++) {
                int k = kr + p * 8;
                *(float4*)&ws[k][nq] = *(const float4*)&W[(k0 + k) * FDIM + h * 128 + nq];
            }
        }
        __syncthreads();
#pragma unroll
        for (int kk = 0; kk < 32; kk++) {
            unsigned long long rn01 = *(const unsigned long long*)&ws[kk][tc * 4];
            unsigned long long rn23 = *(const unsigned long long*)&ws[kk][tc * 4 + 2];
#pragma unroll
            for (int i = 0; i < 8; i++) {
                float rm = xs[kk][tr * 8 + i];
                unsigned long long am;
                asm("mov.b64 %0, {%1, %1};" : "=l"(am) : "r"(__float_as_uint(rm)));
                asm("fma.rn.f32x2 %0, %1, %2, %3;"
                    : "=l"(acc2[i][0]) : "l"(am), "l"(rn01), "l"(acc2[i][0]));
                asm("fma.rn.f32x2 %0, %1, %2, %3;"
                    : "=l"(acc2[i][1]) : "l"(am), "l"(rn23), "l"(acc2[i][1]));
            }
        }
        __syncthreads();
    }

    // epilogue: bias, store Wh (fp32 + fp16 mirror), fused s/t dot + warp reduce
    float4 bb = *(const float4*)&b[h * 128 + tc * 4];
    float as0 = a[tc * 4 + 0], as1 = a[tc * 4 + 1], as2 = a[tc * 4 + 2], as3 = a[tc * 4 + 3];
    float at0 = a[128 + tc * 4 + 0], at1 = a[128 + tc * 4 + 1];
    float at2 = a[128 + tc * 4 + 2], at3 = a[128 + tc * 4 + 3];

#pragma unroll
    for (int i = 0; i < 8; i++) {
        int grow = row0 + tr * 8 + i;
        unsigned int u0, u1, u2, u3;
        asm("mov.b64 {%0, %1}, %2;" : "=r"(u0), "=r"(u1) : "l"(acc2[i][0]));
        asm("mov.b64 {%0, %1}, %2;" : "=r"(u2), "=r"(u3) : "l"(acc2[i][1]));
        float f0 = __uint_as_float(u0) + bb.x;
        float f1 = __uint_as_float(u1) + bb.y;
        float f2 = __uint_as_float(u2) + bb.z;
        float f3 = __uint_as_float(u3) + bb.w;
        float ps = f0 * as0 + f1 * as1 + f2 * as2 + f3 * as3;
        float pt = f0 * at0 + f1 * at1 + f2 * at2 + f3 * at3;
#pragma unroll
        for (int off = 16; off > 0; off >>= 1) {
            ps += __shfl_down_sync(0xffffffffu, ps, off);
            pt += __shfl_down_sync(0xffffffffu, pt, off);
        }
        if (grow < NN) {
            *(float4*)&g_Wh[grow * FDIM + h * 128 + tc * 4] = make_float4(f0, f1, f2, f3);
            __half2 p01 = __floats2half2_rn(f0, f1);
            __half2 p23 = __floats2half2_rn(f2, f3);
            __half2* hp = (__half2*)&g_Whh[grow * FDIM + h * 128 + tc * 4];
            hp[0] = p01;
            hp[1] = p23;
            if (tc == 0) {
                g_s[grow * 2 + h] = ps;
                g_t[grow * 2 + h] = pt;
            }
        }
    }
}

// ---------------- per-node online softmax + aggregation --------------------
// 1 warp/node; lane owns 8 contiguous halfs (16B) -> 1 LDG.128 per edge/lane.
// Lanes 0-15: head 0 (cols 0-127); lanes 16-31: head 1 (cols 128-255).
__global__ __launch_bounds__(512) void k_agg(float* __restrict__ out) {
    int gwarp = (blockIdx.x * blockDim.x + threadIdx.x) >> 5;
    int lane  = threadIdx.x & 31;
    if (gwarp >= NN) return;
    int n = gwarp;
    int start = g_off[n];
    int end   = g_off[n + 1];
    int h     = lane >> 4;
    int col   = lane * 8;

    if (end == start) {  // deg == 0 -> h' = Wh (fp32 source)
        const float4* src = (const float4*)&g_Wh[n * FDIM + col];
        float4* dst = (float4*)&out[n * FDIM + col];
        dst[0] = src[0];
        dst[1] = src[1];
        return;
    }

    const uint4* __restrict__ whh = (const uint4*)g_Whh;   // row = 32 uint4
    float ss = g_s[n * 2 + h];
    float m = -INFINITY, d = 0.f;
    float f[8];
#pragma unroll
    for (int k = 0; k < 8; k++) f[k] = 0.f;

    int i = start;
    for (; i + 3 < end; i += 4) {
        int d0i = g_dst[i],     d1i = g_dst[i + 1];
        int d2i = g_dst[i + 2], d3i = g_dst[i + 3];
        uint4 v0 = whh[d0i * 32 + lane];
        uint4 v1 = whh[d1i * 32 + lane];
        uint4 v2 = whh[d2i * 32 + lane];
        uint4 v3 = whh[d3i * 32 + lane];
        float t0 = g_t[d0i * 2 + h], t1 = g_t[d1i * 2 + h];
        float t2 = g_t[d2i * 2 + h], t3 = g_t[d3i * 2 + h];

        float e0 = ss + t0; e0 = (e0 > 0.f) ? e0 : 0.2f * e0;
        float e1 = ss + t1; e1 = (e1 > 0.f) ? e1 : 0.2f * e1;
        float e2 = ss + t2; e2 = (e2 > 0.f) ? e2 : 0.2f * e2;
        float e3 = ss + t3; e3 = (e3 > 0.f) ? e3 : 0.2f * e3;

        float nm = fmaxf(fmaxf(m, fmaxf(e0, e1)), fmaxf(e2, e3));
        float c  = __expf(m - nm);
        float w0 = __expf(e0 - nm), w1 = __expf(e1 - nm);
        float w2 = __expf(e2 - nm), w3 = __expf(e3 - nm);
        d = d * c + w0 + w1 + w2 + w3;
        m = nm;

        const uint32_t* p0 = &v0.x;
        const uint32_t* p1 = &v1.x;
        const uint32_t* p2 = &v2.x;
        const uint32_t* p3 = &v3.x;
#pragma unroll
        for (int q = 0; q < 4; q++) {
            float2 a0 = __half22float2(*(const __half2*)&p0[q]);
            float2 a1 = __half22float2(*(const __half2*)&p1[q]);
            float2 a2 = __half22float2(*(const __half2*)&p2[q]);
            float2 a3 = __half22float2(*(const __half2*)&p3[q]);
            f[q * 2 + 0] = f[q * 2 + 0] * c + w0 * a0.x + w1 * a1.x + w2 * a2.x + w3 * a3.x;
            f[q * 2 + 1] = f[q * 2 + 1] * c + w0 * a0.y + w1 * a1.y + w2 * a2.y + w3 * a3.y;
        }
    }
    for (; i < end; i++) {
        int dd = g_dst[i];
        uint4 v = whh[dd * 32 + lane];
        float tt = g_t[dd * 2 + h];
        float e = ss + tt; e = (e > 0.f) ? e : 0.2f * e;
        float nm = fmaxf(m, e);
        float c  = __expf(m - nm);
        float w  = __expf(e - nm);
        d = d * c + w;
        m = nm;
        const uint32_t* p = &v.x;
#pragma unroll
        for (int q = 0; q < 4; q++) {
            float2 av = __half22float2(*(const __half2*)&p[q]);
            f[q * 2 + 0] = f[q * 2 + 0] * c + w * av.x;
            f[q * 2 + 1] = f[q * 2 + 1] * c + w * av.y;
        }
    }

    float inv = 1.f / d;
    float4 o0 = make_float4(f[0] * inv, f[1] * inv, f[2] * inv, f[3] * inv);
    float4 o1 = make_float4(f[4] * inv, f[5] * inv, f[6] * inv, f[7] * inv);
    float4* dst = (float4*)&out[n * FDIM + col];
    dst[0] = o0;
    dst[1] = o1;
}

// ---------------- launch (fork-join: CSR build overlaps GEMM) --------------
static cudaStream_t g_s1 = 0;
static cudaEvent_t  g_evFork = 0, g_evJoin = 0;

extern "C" void kernel_launch(void* const* d_in, const int* in_sizes, int n_in,
                              void* d_out, int out_size) {
    const float* x  = (const float*)d_in[0];
    const int*   ei = (const int*)d_in[1];     // int32: JAX x64-disabled
    const float* W  = (const float*)d_in[2];
    const float* b  = (const float*)d_in[3];
    const float* a  = (const float*)d_in[4];
    float*       out = (float*)d_out;

    if (g_s1 == 0) {   // one-time resource setup (first call is eager, pre-capture)
        cudaStreamCreateWithFlags(&g_s1, cudaStreamNonBlocking);
        cudaEventCreateWithFlags(&g_evFork, cudaEventDisableTiming);
        cudaEventCreateWithFlags(&g_evJoin, cudaEventDisableTiming);
    }

    // fork: CSR chain on s1, independent of GEMM
    cudaEventRecord(g_evFork, 0);
    cudaStreamWaitEvent(g_s1, g_evFork, 0);

    k_zero<<<(NN + 255) / 256, 256, 0, g_s1>>>();
    k_count<<<(NE + 255) / 256, 256, 0, g_s1>>>(ei);
    k_scan1<<<SCAN_BLKS, 256, 0, g_s1>>>();
    k_scan2<<<1, 64, 0, g_s1>>>();
    k_scan3<<<SCAN_BLKS, 256, 0, g_s1>>>();
    k_scatter<<<(NE + 255) / 256, 256, 0, g_s1>>>(ei);
    cudaEventRecord(g_evJoin, g_s1);

    // GEMM on the main stream, concurrent with the CSR chain
    dim3 gg((NN + 63) / 64, 2);
    k_gemm<<<gg, 256>>>(x, W, b, a);

    // join, then aggregate
    cudaStreamWaitEvent(0, g_evJoin, 0);
    k_agg<<<(NN * 32 + 511) / 512, 512>>>(out);
}